// round 1
// baseline (speedup 1.0000x reference)
#include <cuda_runtime.h>
#include <math.h>

// CTC loss forward: B=64, T=1000, C=128 (blank=127), L=100, S=201
// One CTA per batch element; one thread per extended-label position.
// alpha kept in registers; shared memory for neighbor exchange (double
// buffered -> one __syncthreads per time step) and per-step log-prob row.

#define Bc 64
#define Tc 1000
#define Cc 128
#define Lc 100
#define Sc 201   // 2*L + 1

#define NEGV (-1e30f)
#define EPSV (1e-7f)

__global__ __launch_bounds__(256, 1)
void ctc_loss_kernel(const int* __restrict__ y_true,
                     const float* __restrict__ y_pred,
                     const int* __restrict__ input_len,
                     const int* __restrict__ label_len,
                     float* __restrict__ out)
{
    const int b   = blockIdx.x;
    const int tid = threadIdx.x;
    const int s   = tid;              // extended-label position this thread owns

    __shared__ float lsh[2][Cc];      // log(y_pred[b,t,:]+eps), double buffered
    __shared__ float abuf[2][Sc];     // alpha exchange, double buffered
    __shared__ int   labels[Lc];

    if (tid < Lc) labels[tid] = y_true[b * Lc + tid];
    __syncthreads();

    // Per-thread extended label class + skip flag (constant over t).
    int  myclass = Cc - 1;            // blank
    bool skip    = false;
    if (s < Sc && (s & 1)) {
        int j   = (s - 1) >> 1;
        myclass = labels[j];
        skip    = (j >= 1) && (labels[j] != labels[j - 1]);  // s>=3 guaranteed when j>=1
    }

    int Tb = input_len[b];
    if (Tb > Tc) Tb = Tc;             // steps applied only while t < input_len

    const float* ypb = y_pred + (size_t)b * Tc * Cc;

    // t = 0 init: alpha[0] = lp(0, ext[0]), alpha[1] = lp(0, ext[1]), else NEG
    float alpha = NEGV;
    if (s < 2) {
        alpha = logf(ypb[myclass] + EPSV);
    }

    // Distance-2 register prefetch of probability rows (covers L2-hit latency).
    float v0 = 0.f, v1 = 0.f;
    if (tid < Cc) {
        if (Tb > 1) v0 = ypb[(size_t)1 * Cc + tid];
        if (Tb > 2) v1 = ypb[(size_t)2 * Cc + tid];
    }

    for (int t = 1; t < Tb; ++t) {
        const int p = t & 1;
        // Threads 0..127: produce log row for this step, prefetch row t+2.
        if (tid < Cc) {
            lsh[p][tid] = logf(v0 + EPSV);
            v0 = v1;
            if (t + 2 < Tb) v1 = ypb[(size_t)(t + 2) * Cc + tid];
        }
        // Publish current alpha for neighbor reads.
        if (s < Sc) abuf[p][s] = alpha;
        __syncthreads();
        if (s < Sc) {
            float lp = lsh[p][myclass];
            float a0 = alpha;
            float a1 = (s >= 1) ? abuf[p][s - 1] : NEGV;
            float a2 = skip     ? abuf[p][s - 2] : NEGV;  // skip implies s>=3
            // 3-way logaddexp (single exp/log chain instead of two nested)
            float m  = fmaxf(a0, fmaxf(a1, a2));
            float sm = expf(a0 - m) + expf(a1 - m) + expf(a2 - m);
            alpha = m + logf(sm) + lp;
        }
        // Next iteration writes the other buffers -> no second sync needed.
    }

    // Final gather: loss = -logaddexp(alpha[2*ll], alpha[2*ll-1])
    __syncthreads();                  // last readers of abuf[p] done before reuse
    if (s < Sc) abuf[0][s] = alpha;
    __syncthreads();
    if (tid == 0) {
        int   ll = label_len[b];
        float aL = abuf[0][2 * ll];
        float aP = abuf[0][2 * ll - 1];
        float m  = fmaxf(aL, aP);
        out[b] = -(m + logf(expf(aL - m) + expf(aP - m)));
    }
}

extern "C" void kernel_launch(void* const* d_in, const int* in_sizes, int n_in,
                              void* d_out, int out_size)
{
    const int*   y_true    = (const int*)  d_in[0];  // [B,L] int32
    const float* y_pred    = (const float*)d_in[1];  // [B,T,C] float32
    const int*   input_len = (const int*)  d_in[2];  // [B] int32
    const int*   label_len = (const int*)  d_in[3];  // [B] int32
    float*       out       = (float*)d_out;          // [B,1] float32

    ctc_loss_kernel<<<Bc, 256>>>(y_true, y_pred, input_len, label_len, out);
}

// round 3
// speedup vs baseline: 2.0530x; 2.0530x over previous
#include <cuda_runtime.h>
#include <math.h>

// CTC loss forward: B=64, T=1000, C=128 (blank=127), L=100, S=201
// One CTA per batch element, one thread per extended-label position.
// All log-domain math in base 2 using raw MUFU ex2/lg2 approx instructions.
// Per-thread gather of its own class probability with depth-3 prefetch
// pipeline (load + lg2 conversion fully off the serial critical path).
// Branchless inner loop: alpha buffer front-padded with NEG so s-1/s-2
// reads need no guards; 224 threads (7 warps), threads >= 201 compute
// harmless values that are never read.

#define Bc 64
#define Tc 1000
#define Cc 128
#define Lc 100
#define Sc 201          // 2*L + 1
#define NTHREADS 224    // 7 warps, >= Sc
#define PAD 2

#define NEGV (-1e30f)
#define EPSV (1e-7f)
#define LN2F 0.6931471805599453f

__device__ __forceinline__ float ex2a(float x) {
    float y; asm("ex2.approx.f32 %0, %1;" : "=f"(y) : "f"(x)); return y;
}
__device__ __forceinline__ float lg2a(float x) {
    float y; asm("lg2.approx.f32 %0, %1;" : "=f"(y) : "f"(x)); return y;
}

__global__ __launch_bounds__(NTHREADS, 1)
void ctc_loss_kernel(const int* __restrict__ y_true,
                     const float* __restrict__ y_pred,
                     const int* __restrict__ input_len,
                     const int* __restrict__ label_len,
                     float* __restrict__ out)
{
    const int b   = blockIdx.x;
    const int s   = threadIdx.x;          // extended-label position (0..223)

    __shared__ float abuf_raw[2][PAD + NTHREADS];   // front-padded alpha exchange
    __shared__ int   labels[Lc];

    float* ab0 = &abuf_raw[0][PAD];
    float* ab1 = &abuf_raw[1][PAD];

    if (s < Lc) labels[s] = y_true[b * Lc + s];
    if (s < PAD) { abuf_raw[0][s] = NEGV; abuf_raw[1][s] = NEGV; }
    __syncthreads();

    // Per-thread extended label class + skip flag (constant over t).
    int  myclass = Cc - 1;                // blank
    bool skip    = false;
    if (s < Sc && (s & 1)) {
        int j   = (s - 1) >> 1;
        myclass = labels[j];
        skip    = (j >= 1) && (labels[j] != labels[j - 1]);
    }

    int Tb = input_len[b];
    if (Tb > Tc) Tb = Tc;

    const float* col = y_pred + (size_t)b * Tc * Cc + myclass;  // this thread's column

    // t = 0 init (base-2 logs): alpha[0], alpha[1] = lg2(p + eps), else NEG
    float alpha = (s < 2) ? lg2a(col[0] + EPSV) : NEGV;

    // Depth-3 pipeline: l0 = lp for step t, l1 for t+1, v = raw prob for t+2.
    // Indices clamped to Tb-1 so loads stay unconditional (values past the
    // live range are computed but never affect frozen alpha -- loop stops at Tb).
    const int tmax = Tb - 1;
    float l0 = lg2a(col[(size_t)min(1, tmax) * Cc] + EPSV);
    float l1 = lg2a(col[(size_t)min(2, tmax) * Cc] + EPSV);
    float v  = col[(size_t)min(3, tmax) * Cc];

    for (int t = 1; t < Tb; ++t) {
        float lp = l0;
        l0 = l1;
        l1 = lg2a(v + EPSV);                       // off critical path
        v  = col[(size_t)min(t + 3, tmax) * Cc];   // unconditional prefetch

        float* ab = (t & 1) ? ab1 : ab0;
        ab[s] = alpha;                             // publish previous alpha
        __syncthreads();
        float a0 = alpha;
        float a1 = ab[s - 1];                      // padded: safe at s=0
        float a2 = skip ? ab[s - 2] : NEGV;
        float m  = fmaxf(a0, fmaxf(a1, a2));
        float sm = ex2a(a0 - m) + ex2a(a1 - m) + ex2a(a2 - m);
        alpha = m + lg2a(sm) + lp;
        // next iteration writes the other buffer -> no second sync needed
    }

    // Final gather: loss = -ln2 * log2addexp(alpha[2*ll], alpha[2*ll-1])
    __syncthreads();
    ab0[s] = alpha;
    __syncthreads();
    if (s == 0) {
        int   ll = label_len[b];
        float aL = ab0[2 * ll];
        float aP = ab0[2 * ll - 1];
        float m  = fmaxf(aL, aP);
        out[b] = -LN2F * (m + lg2a(ex2a(aL - m) + ex2a(aP - m)));
    }
}

extern "C" void kernel_launch(void* const* d_in, const int* in_sizes, int n_in,
                              void* d_out, int out_size)
{
    const int*   y_true    = (const int*)  d_in[0];  // [B,L] int32
    const float* y_pred    = (const float*)d_in[1];  // [B,T,C] float32
    const int*   input_len = (const int*)  d_in[2];  // [B] int32
    const int*   label_len = (const int*)  d_in[3];  // [B] int32
    float*       out       = (float*)d_out;          // [B,1] float32

    ctc_loss_kernel<<<Bc, NTHREADS>>>(y_true, y_pred, input_len, label_len, out);
}